// round 1
// baseline (speedup 1.0000x reference)
#include <cuda_runtime.h>
#include <math.h>

// Problem constants
#define EMBED   512
#define NHEAD   8
#define DHEAD   64
#define LQ      2048
#define LK      2048
#define BATCH   4
#define MROWS   (BATCH * LQ)   // 8192
#define SCALE   0.125f          // 1/sqrt(64)

// ---------------- scratch (device globals; no allocation allowed) -----------
__device__ float g_Q[MROWS * EMBED];
__device__ float g_K[MROWS * EMBED];
__device__ float g_V[MROWS * EMBED];
__device__ float g_C[MROWS * EMBED];

// ---------------------------------------------------------------------------
// SGEMM: C[M,512] = A[M,512] @ W[512,512] + bias[512]
// 64x64 tile, BK=16, 256 threads, 4x4 register micro-tile.
// ---------------------------------------------------------------------------
__global__ void __launch_bounds__(256) sgemm_bias_kernel(
    const float* __restrict__ A, const float* __restrict__ W,
    const float* __restrict__ bias, float* __restrict__ C)
{
    constexpr int BM = 64, BN = 64, BK = 16;
    __shared__ float As[BK][BM + 1];   // As[k][m], padded
    __shared__ float Ws[BK][BN];       // Ws[k][n]

    const int t  = threadIdx.x;
    const int m0 = blockIdx.y * BM;
    const int n0 = blockIdx.x * BN;
    const int ty = t >> 4;     // 0..15
    const int tx = t & 15;     // 0..15

    float acc[4][4] = {};

    for (int k0 = 0; k0 < 512; k0 += BK) {
        __syncthreads();
        // load A tile (64 rows x 16 cols), transpose into As[k][m]
        #pragma unroll
        for (int p = 0; p < 4; p++) {
            int r = (t >> 4) + p * 16;   // 0..63
            int c = t & 15;              // 0..15
            As[c][r] = A[(size_t)(m0 + r) * 512 + k0 + c];
        }
        // load W tile (16 rows x 64 cols)
        #pragma unroll
        for (int p = 0; p < 4; p++) {
            int r = (t >> 6) + p * 4;    // 0..15
            int c = t & 63;              // 0..63
            Ws[r][c] = W[(size_t)(k0 + r) * 512 + n0 + c];
        }
        __syncthreads();

        #pragma unroll
        for (int k = 0; k < BK; k++) {
            float a[4], b[4];
            #pragma unroll
            for (int i = 0; i < 4; i++) a[i] = As[k][ty * 4 + i];
            #pragma unroll
            for (int j = 0; j < 4; j++) b[j] = Ws[k][tx * 4 + j];
            #pragma unroll
            for (int i = 0; i < 4; i++)
                #pragma unroll
                for (int j = 0; j < 4; j++)
                    acc[i][j] = fmaf(a[i], b[j], acc[i][j]);
        }
    }

    #pragma unroll
    for (int i = 0; i < 4; i++) {
        int m = m0 + ty * 4 + i;
        #pragma unroll
        for (int j = 0; j < 4; j++) {
            int n = n0 + tx * 4 + j;
            C[(size_t)m * 512 + n] = acc[i][j] + bias[n];
        }
    }
}

// ---------------------------------------------------------------------------
// Flash attention, fp32, per (64-query tile, head, batch) block, 256 threads.
// smem: Qs[64][64], KsT[64][68] (K transposed, dim-major), Vs[64][64],
//       Ss[64][65] (padded scores/probs).
// S phase : 16x16 thread grid, 4x4 output patch each.
// Softmax/PV: thread t owns query row (t>>2), dim slice ((t&3)*16 .. +15).
// ---------------------------------------------------------------------------
#define SM_QS   0
#define SM_KST  (64 * 64)
#define SM_VS   (SM_KST + 64 * 68)
#define SM_SS   (SM_VS + 64 * 64)
#define SM_FLOATS (SM_SS + 64 * 65)

__global__ void __launch_bounds__(256) flash_attn_kernel(
    const float* __restrict__ Q, const float* __restrict__ K,
    const float* __restrict__ V, float* __restrict__ O)
{
    extern __shared__ float sm[];
    float* Qs  = sm + SM_QS;    // [64][64]
    float* KsT = sm + SM_KST;   // [64][68]  KsT[dim][kv]
    float* Vs  = sm + SM_VS;    // [64][64]
    float* Ss  = sm + SM_SS;    // [64][65]

    const int t  = threadIdx.x;
    const int h  = blockIdx.y;
    const int b  = blockIdx.z;
    const int q0 = blockIdx.x * 64;

    const size_t base_q = ((size_t)b * LQ + q0) * EMBED + h * DHEAD;
    const size_t base_k = ((size_t)b * LK) * EMBED + h * DHEAD;

    // Load + scale Q tile
    #pragma unroll
    for (int i = t; i < 64 * 64; i += 256) {
        int r = i >> 6, c = i & 63;
        Qs[r * 64 + c] = Q[base_q + (size_t)r * EMBED + c] * SCALE;
    }

    // per-row online softmax state (each of the 4 threads of a row keeps a copy)
    const int r_own  = t >> 2;          // query row owned (0..63)
    const int dsl    = (t & 3) * 16;    // dim / col slice
    float m_run = -INFINITY;
    float l_run = 0.0f;
    float acc[16] = {};

    const int ty = t >> 4, tx = t & 15;

    for (int tile = 0; tile < LK / 64; tile++) {
        __syncthreads();   // previous PV reads of Vs/Ss done
        // load K (transposed) and V tiles
        #pragma unroll
        for (int i = t; i < 64 * 64; i += 256) {
            int r = i >> 6, c = i & 63;   // r = kv row, c = dim
            float kv = K[base_k + (size_t)(tile * 64 + r) * EMBED + c];
            KsT[c * 68 + r] = kv;
            Vs[r * 64 + c]  = V[base_k + (size_t)(tile * 64 + r) * EMBED + c];
        }
        __syncthreads();

        // ---- S = Qs @ K^T : 4x4 patch per thread ----
        float s[4][4] = {};
        #pragma unroll 8
        for (int k = 0; k < 64; k++) {
            float a[4];
            #pragma unroll
            for (int i = 0; i < 4; i++) a[i] = Qs[(ty * 4 + i) * 64 + k];
            const float4 bv4 = *(const float4*)(KsT + k * 68 + tx * 4);
            const float bb[4] = {bv4.x, bv4.y, bv4.z, bv4.w};
            #pragma unroll
            for (int i = 0; i < 4; i++)
                #pragma unroll
                for (int j = 0; j < 4; j++)
                    s[i][j] = fmaf(a[i], bb[j], s[i][j]);
        }
        #pragma unroll
        for (int i = 0; i < 4; i++)
            #pragma unroll
            for (int j = 0; j < 4; j++)
                Ss[(ty * 4 + i) * 65 + tx * 4 + j] = s[i][j];
        __syncthreads();

        // ---- online softmax over row r_own, cols [dsl, dsl+16) ----
        float mloc = -INFINITY;
        #pragma unroll
        for (int j = 0; j < 16; j++)
            mloc = fmaxf(mloc, Ss[r_own * 65 + dsl + j]);
        mloc = fmaxf(mloc, __shfl_xor_sync(0xffffffffu, mloc, 1));
        mloc = fmaxf(mloc, __shfl_xor_sync(0xffffffffu, mloc, 2));

        const float m_new = fmaxf(m_run, mloc);
        const float corr  = __expf(m_run - m_new);

        float psum = 0.0f;
        #pragma unroll
        for (int j = 0; j < 16; j++) {
            float p = __expf(Ss[r_own * 65 + dsl + j] - m_new);
            Ss[r_own * 65 + dsl + j] = p;
            psum += p;
        }
        psum += __shfl_xor_sync(0xffffffffu, psum, 1);
        psum += __shfl_xor_sync(0xffffffffu, psum, 2);

        l_run = l_run * corr + psum;
        m_run = m_new;
        #pragma unroll
        for (int i = 0; i < 16; i++) acc[i] *= corr;
        __syncthreads();   // all prob writes visible

        // ---- PV: acc[d] += sum_c p[r][c] * V[c][d] ----
        #pragma unroll 4
        for (int c = 0; c < 64; c++) {
            const float pv = Ss[r_own * 65 + c];
            const float4* vr = (const float4*)(Vs + c * 64 + dsl);
            float4 v0 = vr[0], v1 = vr[1], v2 = vr[2], v3 = vr[3];
            acc[0]  = fmaf(pv, v0.x, acc[0]);   acc[1]  = fmaf(pv, v0.y, acc[1]);
            acc[2]  = fmaf(pv, v0.z, acc[2]);   acc[3]  = fmaf(pv, v0.w, acc[3]);
            acc[4]  = fmaf(pv, v1.x, acc[4]);   acc[5]  = fmaf(pv, v1.y, acc[5]);
            acc[6]  = fmaf(pv, v1.z, acc[6]);   acc[7]  = fmaf(pv, v1.w, acc[7]);
            acc[8]  = fmaf(pv, v2.x, acc[8]);   acc[9]  = fmaf(pv, v2.y, acc[9]);
            acc[10] = fmaf(pv, v2.z, acc[10]);  acc[11] = fmaf(pv, v2.w, acc[11]);
            acc[12] = fmaf(pv, v3.x, acc[12]);  acc[13] = fmaf(pv, v3.y, acc[13]);
            acc[14] = fmaf(pv, v3.z, acc[14]);  acc[15] = fmaf(pv, v3.w, acc[15]);
        }
    }

    // epilogue: normalize and write ctx in merged-head layout
    const float inv = 1.0f / l_run;
    const size_t orow = ((size_t)b * LQ + q0 + r_own) * EMBED + h * DHEAD + dsl;
    #pragma unroll
    for (int i = 0; i < 16; i++)
        O[orow + i] = acc[i] * inv;
}

// ---------------------------------------------------------------------------
extern "C" void kernel_launch(void* const* d_in, const int* in_sizes, int n_in,
                              void* d_out, int out_size)
{
    const float* query = (const float*)d_in[0];
    const float* key   = (const float*)d_in[1];
    const float* value = (const float*)d_in[2];
    const float* wq    = (const float*)d_in[3];
    const float* bq    = (const float*)d_in[4];
    const float* wk    = (const float*)d_in[5];
    const float* bk    = (const float*)d_in[6];
    const float* wv    = (const float*)d_in[7];
    const float* bv    = (const float*)d_in[8];
    const float* wo    = (const float*)d_in[9];
    const float* bo    = (const float*)d_in[10];
    float* out = (float*)d_out;

    float *Qp, *Kp, *Vp, *Cp;
    cudaGetSymbolAddress((void**)&Qp, g_Q);
    cudaGetSymbolAddress((void**)&Kp, g_K);
    cudaGetSymbolAddress((void**)&Vp, g_V);
    cudaGetSymbolAddress((void**)&Cp, g_C);

    dim3 gProj(EMBED / 64, MROWS / 64);   // (8, 128)

    // QKV projections
    sgemm_bias_kernel<<<gProj, 256>>>(query, wq, bq, Qp);
    sgemm_bias_kernel<<<gProj, 256>>>(key,   wk, bk, Kp);
    sgemm_bias_kernel<<<gProj, 256>>>(value, wv, bv, Vp);

    // Flash attention
    size_t shmem = (size_t)SM_FLOATS * sizeof(float);   // ~65.3 KB
    cudaFuncSetAttribute(flash_attn_kernel,
                         cudaFuncAttributeMaxDynamicSharedMemorySize, (int)shmem);
    flash_attn_kernel<<<dim3(LQ / 64, NHEAD, BATCH), 256, shmem>>>(Qp, Kp, Vp, Cp);

    // Output projection
    sgemm_bias_kernel<<<gProj, 256>>>(Cp, wo, bo, out);
}

// round 2
// speedup vs baseline: 4.4518x; 4.4518x over previous
#include <cuda_runtime.h>
#include <math.h>
#include <stdint.h>

#define EMBED   512
#define NHEAD   8
#define DHEAD   64
#define LQ      2048
#define LK      2048
#define BATCH   4
#define MROWS   (BATCH * LQ)
#define SCALE   0.125f

// ---------------- scratch ----------------
__device__ float g_Q[MROWS * EMBED];
__device__ float g_K[MROWS * EMBED];
__device__ float g_V[MROWS * EMBED];
__device__ float g_C[MROWS * EMBED];

// ---------------- helpers ----------------
__device__ __forceinline__ float tf32r(float x) {
    uint32_t u;
    asm("cvt.rna.tf32.f32 %0, %1;" : "=r"(u) : "f"(x));
    return __uint_as_float(u);
}

__device__ __forceinline__ void mma_tf32(float4& d, const float* a, const float* b) {
    asm volatile(
        "mma.sync.aligned.m16n8k8.row.col.f32.tf32.tf32.f32 "
        "{%0,%1,%2,%3}, {%4,%5,%6,%7}, {%8,%9}, {%0,%1,%2,%3};"
        : "+f"(d.x), "+f"(d.y), "+f"(d.z), "+f"(d.w)
        : "r"(__float_as_uint(a[0])), "r"(__float_as_uint(a[1])),
          "r"(__float_as_uint(a[2])), "r"(__float_as_uint(a[3])),
          "r"(__float_as_uint(b[0])), "r"(__float_as_uint(b[1])));
}

// ===========================================================================
// GEMM (3xTF32 split): C[M,512] = A[M,512] @ W[512,512] + bias
// block 128x128, BK=32, 256 thr, 8 warps (2 wm x 4 wn), warp tile 64x32
// ===========================================================================
#define G_AST 36
#define G_WST 136
#define G_AH  0
#define G_AL  (128 * G_AST)
#define G_WH  (2 * 128 * G_AST)
#define G_WL  (2 * 128 * G_AST + 32 * G_WST)
#define G_SMEM_FLOATS (2 * 128 * G_AST + 2 * 32 * G_WST)

__global__ void __launch_bounds__(256, 2) gemm3x_kernel(
    const float* __restrict__ A, const float* __restrict__ W,
    const float* __restrict__ bias, float* __restrict__ C)
{
    extern __shared__ float sm[];
    float* Ah = sm + G_AH;
    float* Al = sm + G_AL;
    float* Wh = sm + G_WH;
    float* Wl = sm + G_WL;

    const int t = threadIdx.x, lane = t & 31, w = t >> 5;
    const int wm = w & 1, wn = w >> 1;
    const int lq = lane >> 2, lc = lane & 3;
    const int m0 = blockIdx.y * 128, n0 = blockIdx.x * 128;

    float4 acc[4][4];
    #pragma unroll
    for (int i = 0; i < 4; i++)
        #pragma unroll
        for (int j = 0; j < 4; j++)
            acc[i][j] = make_float4(0.f, 0.f, 0.f, 0.f);

    const int ar = t >> 3, ac = (t & 7) * 4;     // A tile: 128x32
    const int wr = t >> 5, wc = (t & 31) * 4;    // W tile: 32x128

    for (int k0 = 0; k0 < 512; k0 += 32) {
        __syncthreads();
        #pragma unroll
        for (int p = 0; p < 4; p++) {
            int r = p * 32 + ar;
            float4 v = *(const float4*)(A + (size_t)(m0 + r) * 512 + k0 + ac);
            float4 h, l;
            h.x = tf32r(v.x); l.x = tf32r(v.x - h.x);
            h.y = tf32r(v.y); l.y = tf32r(v.y - h.y);
            h.z = tf32r(v.z); l.z = tf32r(v.z - h.z);
            h.w = tf32r(v.w); l.w = tf32r(v.w - h.w);
            *(float4*)(Ah + r * G_AST + ac) = h;
            *(float4*)(Al + r * G_AST + ac) = l;
        }
        #pragma unroll
        for (int p = 0; p < 4; p++) {
            int r = p * 8 + wr;
            float4 v = *(const float4*)(W + (size_t)(k0 + r) * 512 + n0 + wc);
            float4 h, l;
            h.x = tf32r(v.x); l.x = tf32r(v.x - h.x);
            h.y = tf32r(v.y); l.y = tf32r(v.y - h.y);
            h.z = tf32r(v.z); l.z = tf32r(v.z - h.z);
            h.w = tf32r(v.w); l.w = tf32r(v.w - h.w);
            *(float4*)(Wh + r * G_WST + wc) = h;
            *(float4*)(Wl + r * G_WST + wc) = l;
        }
        __syncthreads();

        #pragma unroll
        for (int ks = 0; ks < 4; ks++) {
            float ah[4][4], al[4][4];
            #pragma unroll
            for (int mi = 0; mi < 4; mi++) {
                int r = wm * 64 + mi * 16 + lq;
                int c = ks * 8 + lc;
                ah[mi][0] = Ah[r * G_AST + c];
                ah[mi][1] = Ah[(r + 8) * G_AST + c];
                ah[mi][2] = Ah[r * G_AST + c + 4];
                ah[mi][3] = Ah[(r + 8) * G_AST + c + 4];
                al[mi][0] = Al[r * G_AST + c];
                al[mi][1] = Al[(r + 8) * G_AST + c];
                al[mi][2] = Al[r * G_AST + c + 4];
                al[mi][3] = Al[(r + 8) * G_AST + c + 4];
            }
            #pragma unroll
            for (int ni = 0; ni < 4; ni++) {
                int k = ks * 8 + lc;
                int n = wn * 32 + ni * 8 + lq;
                float bh[2] = { Wh[k * G_WST + n], Wh[(k + 4) * G_WST + n] };
                float bl[2] = { Wl[k * G_WST + n], Wl[(k + 4) * G_WST + n] };
                #pragma unroll
                for (int mi = 0; mi < 4; mi++) {
                    mma_tf32(acc[mi][ni], ah[mi], bh);
                    mma_tf32(acc[mi][ni], ah[mi], bl);
                    mma_tf32(acc[mi][ni], al[mi], bh);
                }
            }
        }
    }

    #pragma unroll
    for (int mi = 0; mi < 4; mi++) {
        int r = m0 + wm * 64 + mi * 16 + lq;
        #pragma unroll
        for (int ni = 0; ni < 4; ni++) {
            int c = n0 + wn * 32 + ni * 8 + 2 * lc;
            float b0 = bias[c], b1 = bias[c + 1];
            float2 v0 = make_float2(acc[mi][ni].x + b0, acc[mi][ni].y + b1);
            float2 v1 = make_float2(acc[mi][ni].z + b0, acc[mi][ni].w + b1);
            *(float2*)(C + (size_t)r * 512 + c)       = v0;
            *(float2*)(C + (size_t)(r + 8) * 512 + c) = v1;
        }
    }
}

// ===========================================================================
// Flash attention (tf32 mma): 128 queries x 64-kv tiles, per (qtile,head,batch)
// 256 thr, 8 warps (4 wm x 2 wn), warp tile 32x32 for both S and PV.
// ===========================================================================
#define F_QST 68
#define F_SST 68
#define F_KST 68
#define F_VST 72
#define F_QS  0
#define F_SS  (128 * F_QST)
#define F_KS  (F_SS + 128 * F_SST)
#define F_VS  (F_KS + 64 * F_KST)
#define F_MS  (F_VS + 64 * F_VST)
#define F_LS  (F_MS + 128)
#define F_CS  (F_LS + 128)
#define F_SMEM_FLOATS (F_CS + 128)

__global__ void __launch_bounds__(256, 2) flash_tf32_kernel(
    const float* __restrict__ Q, const float* __restrict__ K,
    const float* __restrict__ V, float* __restrict__ O)
{
    extern __shared__ float sm[];
    float* Qs = sm + F_QS;
    float* Ss = sm + F_SS;
    float* Ks = sm + F_KS;
    float* Vs = sm + F_VS;
    float* Ms = sm + F_MS;
    float* Ls = sm + F_LS;
    float* Cs = sm + F_CS;

    const int t = threadIdx.x, lane = t & 31, w = t >> 5;
    const int wm = w & 3, wn = w >> 2;
    const int lq = lane >> 2, lc = lane & 3;
    const int bb_ = blockIdx.z, hh = blockIdx.y;
    const int q0 = blockIdx.x * 128;

    const int lr = t >> 4, lcol = (t & 15) * 4;   // loader coords

    // load Q (128x64), scale + tf32 round
    {
        const size_t base = ((size_t)bb_ * LQ + q0) * EMBED + hh * DHEAD;
        #pragma unroll
        for (int p = 0; p < 8; p++) {
            int r = p * 16 + lr;
            float4 v = *(const float4*)(Q + base + (size_t)r * EMBED + lcol);
            v.x = tf32r(v.x * SCALE); v.y = tf32r(v.y * SCALE);
            v.z = tf32r(v.z * SCALE); v.w = tf32r(v.w * SCALE);
            *(float4*)(Qs + r * F_QST + lcol) = v;
        }
    }
    if (t < 128) { Ms[t] = -INFINITY; Ls[t] = 0.f; }

    float4 o[2][4];
    #pragma unroll
    for (int i = 0; i < 2; i++)
        #pragma unroll
        for (int j = 0; j < 4; j++)
            o[i][j] = make_float4(0.f, 0.f, 0.f, 0.f);

    const size_t kvbase = (size_t)bb_ * LK * EMBED + hh * DHEAD;

    for (int kt = 0; kt < LK / 64; kt++) {
        __syncthreads();
        // load K,V tile (64x64), tf32 round
        #pragma unroll
        for (int p = 0; p < 4; p++) {
            int r = p * 16 + lr;
            size_t g = kvbase + (size_t)(kt * 64 + r) * EMBED + lcol;
            float4 kv = *(const float4*)(K + g);
            kv.x = tf32r(kv.x); kv.y = tf32r(kv.y);
            kv.z = tf32r(kv.z); kv.w = tf32r(kv.w);
            *(float4*)(Ks + r * F_KST + lcol) = kv;
            float4 vv = *(const float4*)(V + g);
            vv.x = tf32r(vv.x); vv.y = tf32r(vv.y);
            vv.z = tf32r(vv.z); vv.w = tf32r(vv.w);
            *(float4*)(Vs + r * F_VST + lcol) = vv;
        }
        __syncthreads();

        // ---- S = Q @ K^T ----
        float4 s[2][4];
        #pragma unroll
        for (int i = 0; i < 2; i++)
            #pragma unroll
            for (int j = 0; j < 4; j++)
                s[i][j] = make_float4(0.f, 0.f, 0.f, 0.f);

        #pragma unroll
        for (int ks = 0; ks < 8; ks++) {
            float a[2][4];
            #pragma unroll
            for (int mi = 0; mi < 2; mi++) {
                int r = wm * 32 + mi * 16 + lq;
                int c = ks * 8 + lc;
                a[mi][0] = Qs[r * F_QST + c];
                a[mi][1] = Qs[(r + 8) * F_QST + c];
                a[mi][2] = Qs[r * F_QST + c + 4];
                a[mi][3] = Qs[(r + 8) * F_QST + c + 4];
            }
            #pragma unroll
            for (int ni = 0; ni < 4; ni++) {
                int n = wn * 32 + ni * 8 + lq;
                int k = ks * 8 + lc;
                float bfr[2] = { Ks[n * F_KST + k], Ks[n * F_KST + k + 4] };
                #pragma unroll
                for (int mi = 0; mi < 2; mi++)
                    mma_tf32(s[mi][ni], a[mi], bfr);
            }
        }
        // write S frags to smem
        #pragma unroll
        for (int mi = 0; mi < 2; mi++) {
            int r = wm * 32 + mi * 16 + lq;
            #pragma unroll
            for (int ni = 0; ni < 4; ni++) {
                int c = wn * 32 + ni * 8 + 2 * lc;
                *(float2*)(Ss + r * F_SST + c)       = make_float2(s[mi][ni].x, s[mi][ni].y);
                *(float2*)(Ss + (r + 8) * F_SST + c) = make_float2(s[mi][ni].z, s[mi][ni].w);
            }
        }
        __syncthreads();

        // ---- online softmax: 2 threads per row ----
        {
            int row = t >> 1, c0 = (t & 1) * 32;
            float* srow = Ss + row * F_SST + c0;
            float4 vb[8];
            float mloc = -INFINITY;
            #pragma unroll
            for (int j = 0; j < 8; j++) {
                vb[j] = *(float4*)(srow + 4 * j);
                mloc = fmaxf(mloc, fmaxf(fmaxf(vb[j].x, vb[j].y), fmaxf(vb[j].z, vb[j].w)));
            }
            mloc = fmaxf(mloc, __shfl_xor_sync(0xffffffffu, mloc, 1));
            float mold = Ms[row];
            float mnew = fmaxf(mold, mloc);
            float corr = __expf(mold - mnew);
            float ps = 0.f;
            #pragma unroll
            for (int j = 0; j < 8; j++) {
                float4 v = vb[j];
                v.x = __expf(v.x - mnew); ps += v.x;
                v.y = __expf(v.y - mnew); ps += v.y;
                v.z = __expf(v.z - mnew); ps += v.z;
                v.w = __expf(v.w - mnew); ps += v.w;
                v.x = tf32r(v.x); v.y = tf32r(v.y);
                v.z = tf32r(v.z); v.w = tf32r(v.w);
                *(float4*)(srow + 4 * j) = v;
            }
            ps += __shfl_xor_sync(0xffffffffu, ps, 1);
            if ((t & 1) == 0) {
                Ms[row] = mnew;
                Ls[row] = Ls[row] * corr + ps;
                Cs[row] = corr;
            }
        }
        __syncthreads();

        // ---- rescale O, then O += P @ V ----
        #pragma unroll
        for (int mi = 0; mi < 2; mi++) {
            int r = wm * 32 + mi * 16 + lq;
            float c1 = Cs[r], c2 = Cs[r + 8];
            #pragma unroll
            for (int ni = 0; ni < 4; ni++) {
                o[mi][ni].x *= c1; o[mi][ni].y *= c1;
                o[mi][ni].z *= c2; o[mi][ni].w *= c2;
            }
        }
        #pragma unroll
        for (int ks = 0; ks < 8; ks++) {
            float a[2][4];
            #pragma unroll
            for (int mi = 0; mi < 2; mi++) {
                int r = wm * 32 + mi * 16 + lq;
                int c = ks * 8 + lc;
                a[mi][0] = Ss[r * F_SST + c];
                a[mi][1] = Ss[(r + 8) * F_SST + c];
                a[mi][2] = Ss[r * F_SST + c + 4];
                a[mi][3] = Ss[(r + 8) * F_SST + c + 4];
            }
            #pragma unroll
            for (int ni = 0; ni < 4; ni++) {
                int k = ks * 8 + lc;
                int n = wn * 32 + ni * 8 + lq;
                float bfr[2] = { Vs[k * F_VST + n], Vs[(k + 4) * F_VST + n] };
                #pragma unroll
                for (int mi = 0; mi < 2; mi++)
                    mma_tf32(o[mi][ni], a[mi], bfr);
            }
        }
    }

    __syncthreads();
    // epilogue: normalize, write merged-head ctx
    #pragma unroll
    for (int mi = 0; mi < 2; mi++) {
        int r = wm * 32 + mi * 16 + lq;
        float inv0 = 1.f / Ls[r];
        float inv1 = 1.f / Ls[r + 8];
        size_t g0 = ((size_t)bb_ * LQ + q0 + r) * EMBED + hh * DHEAD;
        #pragma unroll
        for (int ni = 0; ni < 4; ni++) {
            int c = wn * 32 + ni * 8 + 2 * lc;
            *(float2*)(O + g0 + c) =
                make_float2(o[mi][ni].x * inv0, o[mi][ni].y * inv0);
            *(float2*)(O + g0 + (size_t)8 * EMBED + c) =
                make_float2(o[mi][ni].z * inv1, o[mi][ni].w * inv1);
        }
    }
}

// ===========================================================================
extern "C" void kernel_launch(void* const* d_in, const int* in_sizes, int n_in,
                              void* d_out, int out_size)
{
    const float* query = (const float*)d_in[0];
    const float* key   = (const float*)d_in[1];
    const float* value = (const float*)d_in[2];
    const float* wq    = (const float*)d_in[3];
    const float* bq    = (const float*)d_in[4];
    const float* wk    = (const float*)d_in[5];
    const float* bk    = (const float*)d_in[6];
    const float* wv    = (const float*)d_in[7];
    const float* bv    = (const float*)d_in[8];
    const float* wo    = (const float*)d_in[9];
    const float* bo    = (const float*)d_in[10];
    float* out = (float*)d_out;

    float *Qp, *Kp, *Vp, *Cp;
    cudaGetSymbolAddress((void**)&Qp, g_Q);
    cudaGetSymbolAddress((void**)&Kp, g_K);
    cudaGetSymbolAddress((void**)&Vp, g_V);
    cudaGetSymbolAddress((void**)&Cp, g_C);

    const size_t gemm_smem  = (size_t)G_SMEM_FLOATS * sizeof(float);   // ~70 KB
    const size_t flash_smem = (size_t)F_SMEM_FLOATS * sizeof(float);   // ~104.5 KB
    cudaFuncSetAttribute(gemm3x_kernel,
                         cudaFuncAttributeMaxDynamicSharedMemorySize, (int)gemm_smem);
    cudaFuncSetAttribute(flash_tf32_kernel,
                         cudaFuncAttributeMaxDynamicSharedMemorySize, (int)flash_smem);

    dim3 gGemm(EMBED / 128, MROWS / 128);   // (4, 64)

    gemm3x_kernel<<<gGemm, 256, gemm_smem>>>(query, wq, bq, Qp);
    gemm3x_kernel<<<gGemm, 256, gemm_smem>>>(key,   wk, bk, Kp);
    gemm3x_kernel<<<gGemm, 256, gemm_smem>>>(value, wv, bv, Vp);

    flash_tf32_kernel<<<dim3(LQ / 128, NHEAD, BATCH), 256, flash_smem>>>(Qp, Kp, Vp, Cp);

    gemm3x_kernel<<<gGemm, 256, gemm_smem>>>(Cp, wo, bo, out);
}